// round 4
// baseline (speedup 1.0000x reference)
#include <cuda_runtime.h>
#include <cuda_bf16.h>

#define N_NODES 100000
#define N_EDGES 1600000
#define D 64

// Scratch for per-node elu(x*w): 100000*64 floats = 25.6 MB (fits in L2 alongside out)
__device__ float g_emb[N_NODES * D];

// ---------------------------------------------------------------------------
// Kernel 1: emb = elu(x * w), and zero the output buffer.
// One thread per float4 (16 float4 per node row). 1.6M threads.
// ---------------------------------------------------------------------------
__global__ void __launch_bounds__(256) prep_kernel(
    const float* __restrict__ x,     // [N, D]
    const float* __restrict__ w,     // [1, D]
    float* __restrict__ out)         // [N, D] -> zeroed
{
    int i = blockIdx.x * blockDim.x + threadIdx.x;     // float4 index
    const int total = N_NODES * D / 4;                 // 1,600,000
    if (i >= total) return;

    float4 xv = reinterpret_cast<const float4*>(x)[i];
    int c4 = i & 15;                                   // which float4 of the 64-wide row
    float4 wv = reinterpret_cast<const float4*>(w)[c4];

    float4 e;
    {
        float p;
        p = xv.x * wv.x; e.x = p > 0.f ? p : (__expf(p) - 1.f);
        p = xv.y * wv.y; e.y = p > 0.f ? p : (__expf(p) - 1.f);
        p = xv.z * wv.z; e.z = p > 0.f ? p : (__expf(p) - 1.f);
        p = xv.w * wv.w; e.w = p > 0.f ? p : (__expf(p) - 1.f);
    }

    reinterpret_cast<float4*>(g_emb)[i] = e;
    reinterpret_cast<float4*>(out)[i] = make_float4(0.f, 0.f, 0.f, 0.f);
}

// ---------------------------------------------------------------------------
// Kernel 2: edge scatter. 16 threads per edge; each thread moves one float4
// of the 64-float message via a gathered load (L2-resident emb) and a
// vectorized no-return reduction (red.global.add.v4.f32) into out[dst].
// ---------------------------------------------------------------------------
__global__ void __launch_bounds__(256) scatter_kernel(
    const int* __restrict__ src,
    const int* __restrict__ dst,
    float* __restrict__ out)
{
    int t = blockIdx.x * blockDim.x + threadIdx.x;
    int e = t >> 4;                 // edge id
    int part = t & 15;              // which float4 of the row
    if (e >= N_EDGES) return;

    int s = __ldg(src + e);
    int d = __ldg(dst + e);

    const float4* row = reinterpret_cast<const float4*>(g_emb + (size_t)s * D);
    float4 v = __ldg(row + part);

    float* p = out + (size_t)d * D + part * 4;
    asm volatile("red.global.add.v4.f32 [%0], {%1, %2, %3, %4};"
                 :: "l"(p), "f"(v.x), "f"(v.y), "f"(v.z), "f"(v.w)
                 : "memory");
}

extern "C" void kernel_launch(void* const* d_in, const int* in_sizes, int n_in,
                              void* d_out, int out_size)
{
    const float* x   = (const float*)d_in[0];   // graph_embedding [100000, 64]
    const float* w   = (const float*)d_in[1];   // weight [1, 64]
    const int*   src = (const int*)d_in[2];     // [1600000]
    const int*   dst = (const int*)d_in[3];     // [1600000]
    float* out = (float*)d_out;                 // [100000, 64]

    // Phase 1: per-node elu(x*w) into g_emb, zero out.
    {
        const int total4 = N_NODES * D / 4;     // 1.6M float4s
        int threads = 256;
        int blocks = (total4 + threads - 1) / threads;
        prep_kernel<<<blocks, threads>>>(x, w, out);
    }

    // Phase 2: edge scatter with vector atomics.
    {
        const long long total_t = (long long)N_EDGES * 16; // 25.6M threads
        int threads = 256;
        int blocks = (int)((total_t + threads - 1) / threads);
        scatter_kernel<<<blocks, threads>>>(src, dst, out);
    }
}